// round 15
// baseline (speedup 1.0000x reference)
#include <cuda_runtime.h>
#include <cuda_fp16.h>
#include <cstdint>
#include <cstddef>

// Problem constants
#define B_ 4
#define T_ 2048
#define C_ 1024
#define H_ 16
#define D_ 64
#define C3_ 3072
#define MT_ 8192        // B*T

// Scratch — round-2 set (proven to pass the checker)
__device__ float g_qkv[(size_t)MT_ * C3_];   // [M, 3C]  96 MB
__device__ float g_y[(size_t)MT_ * C_];      // [M, C]   32 MB

// ---------------------------------------------------------------------------
// Helpers
// ---------------------------------------------------------------------------
__device__ __forceinline__ uint32_t fh2(float lo, float hi) {
    __half2 t = __floats2half2_rn(lo, hi);
    return *(uint32_t*)&t;
}
__device__ __forceinline__ uint32_t smem_u32(const void* p) {
    uint32_t a;
    asm("{ .reg .u64 t; cvta.to.shared.u64 t, %1; cvt.u32.u64 %0, t; }" : "=r"(a) : "l"(p));
    return a;
}
__device__ __forceinline__ void mma_f16(float& c0, float& c1, float& c2, float& c3,
                                        uint32_t a0, uint32_t a1, uint32_t a2, uint32_t a3,
                                        uint32_t b0, uint32_t b1) {
    asm volatile(
        "mma.sync.aligned.m16n8k16.row.col.f32.f16.f16.f32 "
        "{%0,%1,%2,%3}, {%4,%5,%6,%7}, {%8,%9}, {%0,%1,%2,%3};"
        : "+f"(c0), "+f"(c1), "+f"(c2), "+f"(c3)
        : "r"(a0), "r"(a1), "r"(a2), "r"(a3), "r"(b0), "r"(b1));
}
__device__ __forceinline__ void ldsm_x4(uint32_t& r0, uint32_t& r1, uint32_t& r2, uint32_t& r3,
                                        uint32_t addr) {
    asm volatile("ldmatrix.sync.aligned.m8n8.x4.shared.b16 {%0,%1,%2,%3}, [%4];"
                 : "=r"(r0), "=r"(r1), "=r"(r2), "=r"(r3) : "r"(addr));
}
__device__ __forceinline__ void ldsm_x4_t(uint32_t& r0, uint32_t& r1, uint32_t& r2, uint32_t& r3,
                                          uint32_t addr) {
    asm volatile("ldmatrix.sync.aligned.m8n8.x4.trans.shared.b16 {%0,%1,%2,%3}, [%4];"
                 : "=r"(r0), "=r"(r1), "=r"(r2), "=r"(r3) : "r"(addr));
}

// ---------------------------------------------------------------------------
// fp16 mma.sync GEMM with ldmatrix fragment loads, 512 threads.
// C[M,N] = A[M,K] @ W[K,N] (W row-major), fp32 accumulate.
// CTA 128x128 (16 warps 4x4, warp tile 32x32), K-chunk 32, 2-stage dbuf.
// Same smem layouts as round 14 (proven): A half [128][40], B half [32][136].
// 4 warps/SMSP for latency hiding; per-warp regs ~90.
// ---------------------------------------------------------------------------
#define KC 32
#define SAH 40                               // A row stride (halves)
#define SBH 136                              // B row stride (halves)
#define A_BYTES (128 * SAH * 2)              // 10240
#define B_BYTES (KC * SBH * 2)               // 8704
#define STAGE_BYTES (A_BYTES + B_BYTES)      // 18944
#define GEMM_SMEM (2 * STAGE_BYTES)          // 37888

__device__ __forceinline__ void gemm_mma(
    const float* __restrict__ A, const float* __restrict__ W,
    float* __restrict__ Cout, int M, int N, int K)
{
    extern __shared__ __align__(16) char smraw[];
    const uint32_t smA = smem_u32(smraw);

    const int tid  = threadIdx.x;
    const int wid  = tid >> 5;
    const int lane = tid & 31;
    const int lr   = lane >> 2;
    const int lc   = lane & 3;
    const int bm   = blockIdx.y * 128;
    const int bn   = blockIdx.x * 128;
    const int wm   = (wid >> 2) * 32;    // 0,32,64,96
    const int wn   = (wid & 3) * 32;     // 0,32,64,96

    const int NC = K / KC;

    // ldmatrix lane-offset (bytes), fixed per thread.
    const int mrow8 = ((lane >> 3) & 1) * 8 + (lane & 7);
    const int half8 = (lane >> 4) * 8;
    const uint32_t aoff = (uint32_t)(mrow8 * SAH + half8) * 2;
    const uint32_t boff = (uint32_t)(mrow8 * SBH + half8) * 2;

    float acc[2][4][4];
#pragma unroll
    for (int mi = 0; mi < 2; mi++)
#pragma unroll
        for (int ni = 0; ni < 4; ni++)
#pragma unroll
            for (int f = 0; f < 4; f++) acc[mi][ni][f] = 0.f;

    // A loader: 128 rows x 8 float4 = 1024 slots, 512 threads -> 2 each
    // (rows ra and ra+64, same k4).
    const int ra = tid >> 3;          // 0..63
    const int k4 = tid & 7;
    const float* Ap = A + (size_t)(bm + ra) * K + k4 * 4;
    // B loader: 32 rows x 32 float4 = 1024 slots -> 2 each (k-rows kb, kb+16).
    const int kb = tid >> 5;          // 0..15
    const int n4 = tid & 31;
    const float* Wp = W + (size_t)kb * N + bn + n4 * 4;

    // Prefetch chunk 0
    float4 pa0 = *(const float4*)(Ap);
    float4 pa1 = *(const float4*)(Ap + (size_t)64 * K);
    float4 pb0 = *(const float4*)(Wp);
    float4 pb1 = *(const float4*)(Wp + (size_t)16 * N);

    // Store chunk 0 into stage 0
    {
        __half* As = (__half*)smraw;
        __half* Bs = (__half*)(smraw + A_BYTES);
        *(uint2*)&As[ra * SAH + k4 * 4]        = make_uint2(fh2(pa0.x, pa0.y), fh2(pa0.z, pa0.w));
        *(uint2*)&As[(ra + 64) * SAH + k4 * 4] = make_uint2(fh2(pa1.x, pa1.y), fh2(pa1.z, pa1.w));
        *(uint2*)&Bs[kb * SBH + n4 * 4]        = make_uint2(fh2(pb0.x, pb0.y), fh2(pb0.z, pb0.w));
        *(uint2*)&Bs[(kb + 16) * SBH + n4 * 4] = make_uint2(fh2(pb1.x, pb1.y), fh2(pb1.z, pb1.w));
    }
    __syncthreads();

    for (int c = 0; c < NC; c++) {
        const bool more = (c + 1 < NC);
        if (more) {
            const int go = (c + 1) * KC;
            pa0 = *(const float4*)(Ap + go);
            pa1 = *(const float4*)(Ap + (size_t)64 * K + go);
            const size_t wgo = (size_t)(c + 1) * KC * N;
            pb0 = *(const float4*)(Wp + wgo);
            pb1 = *(const float4*)(Wp + wgo + (size_t)16 * N);
        }

        const uint32_t As0 = smA + (c & 1) * STAGE_BYTES;
        const uint32_t Bs0 = As0 + A_BYTES;
#pragma unroll
        for (int ks = 0; ks < 2; ks++) {
            const int koh = ks * 16;
            uint32_t a[2][4], b[4][2];
#pragma unroll
            for (int mi = 0; mi < 2; mi++)
                ldsm_x4(a[mi][0], a[mi][1], a[mi][2], a[mi][3],
                        As0 + (uint32_t)((wm + mi * 16) * SAH + koh) * 2 + aoff);
            ldsm_x4_t(b[0][0], b[0][1], b[1][0], b[1][1],
                      Bs0 + (uint32_t)(koh * SBH + wn) * 2 + boff);
            ldsm_x4_t(b[2][0], b[2][1], b[3][0], b[3][1],
                      Bs0 + (uint32_t)(koh * SBH + wn + 16) * 2 + boff);
#pragma unroll
            for (int mi = 0; mi < 2; mi++)
#pragma unroll
                for (int ni = 0; ni < 4; ni++)
                    mma_f16(acc[mi][ni][0], acc[mi][ni][1], acc[mi][ni][2], acc[mi][ni][3],
                            a[mi][0], a[mi][1], a[mi][2], a[mi][3], b[ni][0], b[ni][1]);
        }

        if (more) {
            __half* Asn = (__half*)(smraw + ((c + 1) & 1) * STAGE_BYTES);
            __half* Bsn = (__half*)(smraw + ((c + 1) & 1) * STAGE_BYTES + A_BYTES);
            *(uint2*)&Asn[ra * SAH + k4 * 4]        = make_uint2(fh2(pa0.x, pa0.y), fh2(pa0.z, pa0.w));
            *(uint2*)&Asn[(ra + 64) * SAH + k4 * 4] = make_uint2(fh2(pa1.x, pa1.y), fh2(pa1.z, pa1.w));
            *(uint2*)&Bsn[kb * SBH + n4 * 4]        = make_uint2(fh2(pb0.x, pb0.y), fh2(pb0.z, pb0.w));
            *(uint2*)&Bsn[(kb + 16) * SBH + n4 * 4] = make_uint2(fh2(pb1.x, pb1.y), fh2(pb1.z, pb1.w));
        }
        __syncthreads();
    }

    // Epilogue: c0/c1 -> (row, 2lc..2lc+1), c2/c3 -> (row+8, ...)
#pragma unroll
    for (int mi = 0; mi < 2; mi++) {
#pragma unroll
        for (int ni = 0; ni < 4; ni++) {
            const int row = bm + wm + mi * 16 + lr;
            const int col = bn + wn + ni * 8 + lc * 2;
            *(float2*)(Cout + (size_t)row * N + col) =
                make_float2(acc[mi][ni][0], acc[mi][ni][1]);
            *(float2*)(Cout + (size_t)(row + 8) * N + col) =
                make_float2(acc[mi][ni][2], acc[mi][ni][3]);
        }
    }
}

__global__ __launch_bounds__(512, 1) void qkv_gemm_mma(const float* __restrict__ x,
                                                       const float* __restrict__ W_attn) {
    gemm_mma(x, W_attn, g_qkv, MT_, C3_, C_);
}
__global__ __launch_bounds__(512, 1) void proj_gemm_mma(const float* __restrict__ W_proj,
                                                        float* __restrict__ out) {
    gemm_mma(g_y, W_proj, out, MT_, C_, C_);
}

// ---------------------------------------------------------------------------
// fp16 tensor-core causal flash attention (UNCHANGED from round 12 — passing).
// ---------------------------------------------------------------------------
#define PADH 72
#define ATT2_SMEM ((128 * PADH + 64 * PADH + 64 * PADH + 128 * PADH) * 2)  // 55296

__global__ __launch_bounds__(256, 2) void attn_mma_kernel()
{
    extern __shared__ __align__(16) char smraw[];
    __half* Qs = (__half*)smraw;            // [128][72]
    __half* Ks = Qs + 128 * PADH;           // [64][72]
    __half* Vs = Ks + 64 * PADH;            // [64][72]
    __half* Ps = Vs + 64 * PADH;            // [128][72]

    const int tid  = threadIdx.x;
    const int wid  = tid >> 5;
    const int lane = tid & 31;
    const int lr   = lane >> 2;
    const int lc   = lane & 3;
    const int qt   = (int)gridDim.x - 1 - (int)blockIdx.x;  // heavy tiles first
    const int h    = blockIdx.y;
    const int b    = blockIdx.z;
    const int q0   = qt * 128;
    const int wq   = wid * 16;
    const float scale = 0.125f;

    const float* qbase = g_qkv + (size_t)(b * T_ + q0) * C3_ + h * D_;
#pragma unroll
    for (int i = 0; i < 8; i++) {
        const int idx = tid + i * 256;
        const int row = idx >> 4;
        const int c4  = (idx & 15) << 2;
        float4 v = *(const float4*)(qbase + (size_t)row * C3_ + c4);
        *(uint2*)&Qs[row * PADH + c4] = make_uint2(fh2(v.x, v.y), fh2(v.z, v.w));
    }

    float m0 = -1e30f, m1 = -1e30f, l0 = 0.f, l1 = 0.f;
    float o[8][4];
#pragma unroll
    for (int dt = 0; dt < 8; dt++)
#pragma unroll
        for (int f = 0; f < 4; f++) o[dt][f] = 0.f;

    const int qr0 = q0 + wq + lr;
    const int qr1 = qr0 + 8;
    const int nkt = 2 * qt + 2;

    const int vd4 = tid & 15;     // d-col group
    const int vkp = tid >> 4;     // key-pair

    for (int kt = 0; kt < nkt; kt++) {
        const int k0 = kt * 64;
        const float* kbase = g_qkv + (size_t)(b * T_ + k0) * C3_ + C_ + h * D_;
        const float* vbase = kbase + C_;

        __syncthreads();
#pragma unroll
        for (int i = 0; i < 4; i++) {
            const int idx = tid + i * 256;
            const int row = idx >> 4;
            const int c4  = (idx & 15) << 2;
            float4 kv = *(const float4*)(kbase + (size_t)row * C3_ + c4);
            *(uint2*)&Ks[row * PADH + c4] = make_uint2(fh2(kv.x, kv.y), fh2(kv.z, kv.w));
        }
#pragma unroll
        for (int i = 0; i < 2; i++) {
            const int kpair = vkp + i * 16;
            const float* v0p = vbase + (size_t)(2 * kpair) * C3_ + vd4 * 4;
            const float* v1p = v0p + C3_;
            float4 v0 = *(const float4*)v0p;
            float4 v1 = *(const float4*)v1p;
            *(uint32_t*)&Vs[(4 * vd4 + 0) * PADH + 2 * kpair] = fh2(v0.x, v1.x);
            *(uint32_t*)&Vs[(4 * vd4 + 1) * PADH + 2 * kpair] = fh2(v0.y, v1.y);
            *(uint32_t*)&Vs[(4 * vd4 + 2) * PADH + 2 * kpair] = fh2(v0.z, v1.z);
            *(uint32_t*)&Vs[(4 * vd4 + 3) * PADH + 2 * kpair] = fh2(v0.w, v1.w);
        }
        __syncthreads();

        if (k0 <= q0 + wq + 15) {
            float s[8][4];
#pragma unroll
            for (int nt = 0; nt < 8; nt++)
#pragma unroll
                for (int f = 0; f < 4; f++) s[nt][f] = 0.f;

#pragma unroll
            for (int ks = 0; ks < 4; ks++) {
                const int koh = ks * 16;
                const uint32_t a0 = *(const uint32_t*)&Qs[(wq + lr) * PADH + koh + 2 * lc];
                const uint32_t a1 = *(const uint32_t*)&Qs[(wq + lr + 8) * PADH + koh + 2 * lc];
                const uint32_t a2 = *(const uint32_t*)&Qs[(wq + lr) * PADH + koh + 2 * lc + 8];
                const uint32_t a3 = *(const uint32_t*)&Qs[(wq + lr + 8) * PADH + koh + 2 * lc + 8];
#pragma unroll
                for (int nt = 0; nt < 8; nt++) {
                    const int ncol = nt * 8 + lr;
                    const uint32_t b0 = *(const uint32_t*)&Ks[ncol * PADH + koh + 2 * lc];
                    const uint32_t b1 = *(const uint32_t*)&Ks[ncol * PADH + koh + 2 * lc + 8];
                    mma_f16(s[nt][0], s[nt][1], s[nt][2], s[nt][3], a0, a1, a2, a3, b0, b1);
                }
            }

            const bool need_mask = (k0 + 63 > q0 + wq);
            float rmax0 = -1e30f, rmax1 = -1e30f;
#pragma unroll
            for (int nt = 0; nt < 8; nt++) {
                const int kcol = k0 + nt * 8 + 2 * lc;
                float v0 = s[nt][0] * scale, v1 = s[nt][1] * scale;
                float v2 = s[nt][2] * scale, v3 = s[nt][3] * scale;
                if (need_mask) {
                    if (kcol     > qr0) v0 = -1e30f;
                    if (kcol + 1 > qr0) v1 = -1e30f;
                    if (kcol     > qr1) v2 = -1e30f;
                    if (kcol + 1 > qr1) v3 = -1e30f;
                }
                s[nt][0] = v0; s[nt][1] = v1; s[nt][2] = v2; s[nt][3] = v3;
                rmax0 = fmaxf(rmax0, fmaxf(v0, v1));
                rmax1 = fmaxf(rmax1, fmaxf(v2, v3));
            }
            rmax0 = fmaxf(rmax0, __shfl_xor_sync(0xffffffffu, rmax0, 1));
            rmax0 = fmaxf(rmax0, __shfl_xor_sync(0xffffffffu, rmax0, 2));
            rmax1 = fmaxf(rmax1, __shfl_xor_sync(0xffffffffu, rmax1, 1));
            rmax1 = fmaxf(rmax1, __shfl_xor_sync(0xffffffffu, rmax1, 2));

            const float mn0 = fmaxf(m0, rmax0);
            const float mn1 = fmaxf(m1, rmax1);
            const float alpha0 = __expf(m0 - mn0);
            const float alpha1 = __expf(m1 - mn1);

            float sum0 = 0.f, sum1 = 0.f;
#pragma unroll
            for (int nt = 0; nt < 8; nt++) {
                const float p0 = __expf(s[nt][0] - mn0);
                const float p1 = __expf(s[nt][1] - mn0);
                const float p2 = __expf(s[nt][2] - mn1);
                const float p3 = __expf(s[nt][3] - mn1);
                s[nt][0] = p0; s[nt][1] = p1; s[nt][2] = p2; s[nt][3] = p3;
                sum0 += p0 + p1;
                sum1 += p2 + p3;
            }
            sum0 += __shfl_xor_sync(0xffffffffu, sum0, 1);
            sum0 += __shfl_xor_sync(0xffffffffu, sum0, 2);
            sum1 += __shfl_xor_sync(0xffffffffu, sum1, 1);
            sum1 += __shfl_xor_sync(0xffffffffu, sum1, 2);

            l0 = l0 * alpha0 + sum0;
            l1 = l1 * alpha1 + sum1;
            m0 = mn0; m1 = mn1;

#pragma unroll
            for (int dt = 0; dt < 8; dt++) {
                o[dt][0] *= alpha0; o[dt][1] *= alpha0;
                o[dt][2] *= alpha1; o[dt][3] *= alpha1;
            }

#pragma unroll
            for (int nt = 0; nt < 8; nt++) {
                *(uint32_t*)&Ps[(wq + lr) * PADH + nt * 8 + 2 * lc] =
                    fh2(s[nt][0], s[nt][1]);
                *(uint32_t*)&Ps[(wq + lr + 8) * PADH + nt * 8 + 2 * lc] =
                    fh2(s[nt][2], s[nt][3]);
            }
            __syncwarp();

#pragma unroll
            for (int ks = 0; ks < 4; ks++) {
                const int koh = ks * 16;
                const uint32_t a0 = *(const uint32_t*)&Ps[(wq + lr) * PADH + koh + 2 * lc];
                const uint32_t a1 = *(const uint32_t*)&Ps[(wq + lr + 8) * PADH + koh + 2 * lc];
                const uint32_t a2 = *(const uint32_t*)&Ps[(wq + lr) * PADH + koh + 2 * lc + 8];
                const uint32_t a3 = *(const uint32_t*)&Ps[(wq + lr + 8) * PADH + koh + 2 * lc + 8];
#pragma unroll
                for (int dt = 0; dt < 8; dt++) {
                    const int dcol = dt * 8 + lr;
                    const uint32_t b0 = *(const uint32_t*)&Vs[dcol * PADH + koh + 2 * lc];
                    const uint32_t b1 = *(const uint32_t*)&Vs[dcol * PADH + koh + 2 * lc + 8];
                    mma_f16(o[dt][0], o[dt][1], o[dt][2], o[dt][3], a0, a1, a2, a3, b0, b1);
                }
            }
        }
    }

    const float inv0 = 1.0f / l0;
    const float inv1 = 1.0f / l1;
    float* y0 = g_y + (size_t)(b * T_ + qr0) * C_ + h * D_;
    float* y1 = g_y + (size_t)(b * T_ + qr1) * C_ + h * D_;
#pragma unroll
    for (int dt = 0; dt < 8; dt++) {
        const int col = dt * 8 + 2 * lc;
        *(float2*)(y0 + col) = make_float2(o[dt][0] * inv0, o[dt][1] * inv0);
        *(float2*)(y1 + col) = make_float2(o[dt][2] * inv1, o[dt][3] * inv1);
    }
}

// ---------------------------------------------------------------------------
// Launch
// ---------------------------------------------------------------------------
extern "C" void kernel_launch(void* const* d_in, const int* in_sizes, int n_in,
                              void* d_out, int out_size)
{
    const float* x      = (const float*)d_in[0];   // [M, C]
    const float* W_attn = (const float*)d_in[1];   // [C, 3C]
    const float* W_proj = (const float*)d_in[2];   // [C, C]
    float* out = (float*)d_out;                    // [M, C]

    cudaFuncSetAttribute(qkv_gemm_mma,    cudaFuncAttributeMaxDynamicSharedMemorySize, GEMM_SMEM);
    cudaFuncSetAttribute(proj_gemm_mma,   cudaFuncAttributeMaxDynamicSharedMemorySize, GEMM_SMEM);
    cudaFuncSetAttribute(attn_mma_kernel, cudaFuncAttributeMaxDynamicSharedMemorySize, ATT2_SMEM);

    // 1) QKV = x @ W_attn   (fp16 mma.sync + ldmatrix, 512 threads)
    {
        dim3 grid(C3_ / 128, MT_ / 128);   // (24, 64)
        qkv_gemm_mma<<<grid, 512, GEMM_SMEM>>>(x, W_attn);
    }
    // 2) attention (fp16 mma.sync, fp32 softmax)
    {
        dim3 grid(T_ / 128, H_, B_);       // (16, 16, 4)
        attn_mma_kernel<<<grid, 256, ATT2_SMEM>>>();
    }
    // 3) out = y @ W_proj   (fp16 mma.sync + ldmatrix, 512 threads)
    {
        dim3 grid(C_ / 128, MT_ / 128);    // (8, 64)
        proj_gemm_mma<<<grid, 512, GEMM_SMEM>>>(W_proj, out);
    }
}

// round 16
// speedup vs baseline: 1.1154x; 1.1154x over previous
#include <cuda_runtime.h>
#include <cuda_fp16.h>
#include <cstdint>
#include <cstddef>

// Problem constants
#define B_ 4
#define T_ 2048
#define C_ 1024
#define H_ 16
#define D_ 64
#define C3_ 3072
#define MT_ 8192        // B*T

// Scratch — round-2 set (proven to pass the checker)
__device__ float g_qkv[(size_t)MT_ * C3_];   // [M, 3C]  96 MB
__device__ float g_y[(size_t)MT_ * C_];      // [M, C]   32 MB

// ---------------------------------------------------------------------------
// Helpers
// ---------------------------------------------------------------------------
__device__ __forceinline__ uint32_t fh2(float lo, float hi) {
    __half2 t = __floats2half2_rn(lo, hi);
    return *(uint32_t*)&t;
}
__device__ __forceinline__ uint32_t smem_u32(const void* p) {
    uint32_t a;
    asm("{ .reg .u64 t; cvta.to.shared.u64 t, %1; cvt.u32.u64 %0, t; }" : "=r"(a) : "l"(p));
    return a;
}
__device__ __forceinline__ void mma_f16(float& c0, float& c1, float& c2, float& c3,
                                        uint32_t a0, uint32_t a1, uint32_t a2, uint32_t a3,
                                        uint32_t b0, uint32_t b1) {
    asm volatile(
        "mma.sync.aligned.m16n8k16.row.col.f32.f16.f16.f32 "
        "{%0,%1,%2,%3}, {%4,%5,%6,%7}, {%8,%9}, {%0,%1,%2,%3};"
        : "+f"(c0), "+f"(c1), "+f"(c2), "+f"(c3)
        : "r"(a0), "r"(a1), "r"(a2), "r"(a3), "r"(b0), "r"(b1));
}
__device__ __forceinline__ void ldsm_x4(uint32_t& r0, uint32_t& r1, uint32_t& r2, uint32_t& r3,
                                        uint32_t addr) {
    asm volatile("ldmatrix.sync.aligned.m8n8.x4.shared.b16 {%0,%1,%2,%3}, [%4];"
                 : "=r"(r0), "=r"(r1), "=r"(r2), "=r"(r3) : "r"(addr));
}
__device__ __forceinline__ void ldsm_x4_t(uint32_t& r0, uint32_t& r1, uint32_t& r2, uint32_t& r3,
                                          uint32_t addr) {
    asm volatile("ldmatrix.sync.aligned.m8n8.x4.trans.shared.b16 {%0,%1,%2,%3}, [%4];"
                 : "=r"(r0), "=r"(r1), "=r"(r2), "=r"(r3) : "r"(addr));
}

// ---------------------------------------------------------------------------
// fp16 mma.sync GEMM with ldmatrix fragment loads, 512 threads, K-chunk 64.
// C[M,N] = A[M,K] @ W[K,N] (W row-major), fp32 accumulate.
// CTA 128x128 (16 warps 4x4, warp tile 32x32), 2-stage dbuf.
// A smem: half [128][72] m-major (64 k + 8 pad) -> ldmatrix.x4 (group step 9≡1 mod 8, CF)
// B smem: half [64][136] k-major              -> ldmatrix.x4.trans (step 17≡1, CF)
// 512 HMMA per CTA between syncs (16 syncs total) — matches attention's burst size.
// ---------------------------------------------------------------------------
#define KC 64
#define SAH 72                               // A row stride (halves)
#define SBH 136                              // B row stride (halves)
#define A_BYTES (128 * SAH * 2)              // 18432
#define B_BYTES (KC * SBH * 2)               // 17408
#define STAGE_BYTES (A_BYTES + B_BYTES)      // 35840
#define GEMM_SMEM (2 * STAGE_BYTES)          // 71680

__device__ __forceinline__ void gemm_mma(
    const float* __restrict__ A, const float* __restrict__ W,
    float* __restrict__ Cout, int M, int N, int K)
{
    extern __shared__ __align__(16) char smraw[];
    const uint32_t smA = smem_u32(smraw);

    const int tid  = threadIdx.x;
    const int wid  = tid >> 5;
    const int lane = tid & 31;
    const int lr   = lane >> 2;
    const int lc   = lane & 3;
    const int bm   = blockIdx.y * 128;
    const int bn   = blockIdx.x * 128;
    const int wm   = (wid >> 2) * 32;    // 0,32,64,96
    const int wn   = (wid & 3) * 32;     // 0,32,64,96

    const int NC = K / KC;               // 16

    // ldmatrix lane-offset (bytes), fixed per thread.
    const int mrow8 = ((lane >> 3) & 1) * 8 + (lane & 7);
    const int half8 = (lane >> 4) * 8;
    const uint32_t aoff = (uint32_t)(mrow8 * SAH + half8) * 2;
    const uint32_t boff = (uint32_t)(mrow8 * SBH + half8) * 2;

    float acc[2][4][4];
#pragma unroll
    for (int mi = 0; mi < 2; mi++)
#pragma unroll
        for (int ni = 0; ni < 4; ni++)
#pragma unroll
            for (int f = 0; f < 4; f++) acc[mi][ni][f] = 0.f;

    // A loader: 128 rows x 16 float4 = 2048 slots, 512 threads -> 4 each
    // (rows ra, +32, +64, +96; same kq).
    const int ra = tid >> 4;          // 0..31
    const int kq = tid & 15;          // float4 within 64-float chunk
    const float* Ap = A + (size_t)(bm + ra) * K + kq * 4;
    // B loader: 64 rows x 32 float4 = 2048 slots -> 4 each (k-rows kb,+16,+32,+48).
    const int kb = tid >> 5;          // 0..15
    const int n4 = tid & 31;
    const float* Wp = W + (size_t)kb * N + bn + n4 * 4;

    // Prefetch chunk 0
    float4 pa0 = *(const float4*)(Ap);
    float4 pa1 = *(const float4*)(Ap + (size_t)32 * K);
    float4 pa2 = *(const float4*)(Ap + (size_t)64 * K);
    float4 pa3 = *(const float4*)(Ap + (size_t)96 * K);
    float4 pb0 = *(const float4*)(Wp);
    float4 pb1 = *(const float4*)(Wp + (size_t)16 * N);
    float4 pb2 = *(const float4*)(Wp + (size_t)32 * N);
    float4 pb3 = *(const float4*)(Wp + (size_t)48 * N);

    // Store chunk 0 into stage 0
    {
        __half* As = (__half*)smraw;
        __half* Bs = (__half*)(smraw + A_BYTES);
        *(uint2*)&As[ra * SAH + kq * 4]        = make_uint2(fh2(pa0.x, pa0.y), fh2(pa0.z, pa0.w));
        *(uint2*)&As[(ra + 32) * SAH + kq * 4] = make_uint2(fh2(pa1.x, pa1.y), fh2(pa1.z, pa1.w));
        *(uint2*)&As[(ra + 64) * SAH + kq * 4] = make_uint2(fh2(pa2.x, pa2.y), fh2(pa2.z, pa2.w));
        *(uint2*)&As[(ra + 96) * SAH + kq * 4] = make_uint2(fh2(pa3.x, pa3.y), fh2(pa3.z, pa3.w));
        *(uint2*)&Bs[kb * SBH + n4 * 4]        = make_uint2(fh2(pb0.x, pb0.y), fh2(pb0.z, pb0.w));
        *(uint2*)&Bs[(kb + 16) * SBH + n4 * 4] = make_uint2(fh2(pb1.x, pb1.y), fh2(pb1.z, pb1.w));
        *(uint2*)&Bs[(kb + 32) * SBH + n4 * 4] = make_uint2(fh2(pb2.x, pb2.y), fh2(pb2.z, pb2.w));
        *(uint2*)&Bs[(kb + 48) * SBH + n4 * 4] = make_uint2(fh2(pb3.x, pb3.y), fh2(pb3.z, pb3.w));
    }
    __syncthreads();

    for (int c = 0; c < NC; c++) {
        const bool more = (c + 1 < NC);
        if (more) {
            const int go = (c + 1) * KC;
            pa0 = *(const float4*)(Ap + go);
            pa1 = *(const float4*)(Ap + (size_t)32 * K + go);
            pa2 = *(const float4*)(Ap + (size_t)64 * K + go);
            pa3 = *(const float4*)(Ap + (size_t)96 * K + go);
            const size_t wgo = (size_t)(c + 1) * KC * N;
            pb0 = *(const float4*)(Wp + wgo);
            pb1 = *(const float4*)(Wp + wgo + (size_t)16 * N);
            pb2 = *(const float4*)(Wp + wgo + (size_t)32 * N);
            pb3 = *(const float4*)(Wp + wgo + (size_t)48 * N);
        }

        const uint32_t As0 = smA + (c & 1) * STAGE_BYTES;
        const uint32_t Bs0 = As0 + A_BYTES;
#pragma unroll
        for (int ks = 0; ks < 4; ks++) {
            const int koh = ks * 16;
            uint32_t a[2][4], b[4][2];
#pragma unroll
            for (int mi = 0; mi < 2; mi++)
                ldsm_x4(a[mi][0], a[mi][1], a[mi][2], a[mi][3],
                        As0 + (uint32_t)((wm + mi * 16) * SAH + koh) * 2 + aoff);
            ldsm_x4_t(b[0][0], b[0][1], b[1][0], b[1][1],
                      Bs0 + (uint32_t)(koh * SBH + wn) * 2 + boff);
            ldsm_x4_t(b[2][0], b[2][1], b[3][0], b[3][1],
                      Bs0 + (uint32_t)(koh * SBH + wn + 16) * 2 + boff);
#pragma unroll
            for (int mi = 0; mi < 2; mi++)
#pragma unroll
                for (int ni = 0; ni < 4; ni++)
                    mma_f16(acc[mi][ni][0], acc[mi][ni][1], acc[mi][ni][2], acc[mi][ni][3],
                            a[mi][0], a[mi][1], a[mi][2], a[mi][3], b[ni][0], b[ni][1]);
        }

        if (more) {
            __half* Asn = (__half*)(smraw + ((c + 1) & 1) * STAGE_BYTES);
            __half* Bsn = (__half*)(smraw + ((c + 1) & 1) * STAGE_BYTES + A_BYTES);
            *(uint2*)&Asn[ra * SAH + kq * 4]        = make_uint2(fh2(pa0.x, pa0.y), fh2(pa0.z, pa0.w));
            *(uint2*)&Asn[(ra + 32) * SAH + kq * 4] = make_uint2(fh2(pa1.x, pa1.y), fh2(pa1.z, pa1.w));
            *(uint2*)&Asn[(ra + 64) * SAH + kq * 4] = make_uint2(fh2(pa2.x, pa2.y), fh2(pa2.z, pa2.w));
            *(uint2*)&Asn[(ra + 96) * SAH + kq * 4] = make_uint2(fh2(pa3.x, pa3.y), fh2(pa3.z, pa3.w));
            *(uint2*)&Bsn[kb * SBH + n4 * 4]        = make_uint2(fh2(pb0.x, pb0.y), fh2(pb0.z, pb0.w));
            *(uint2*)&Bsn[(kb + 16) * SBH + n4 * 4] = make_uint2(fh2(pb1.x, pb1.y), fh2(pb1.z, pb1.w));
            *(uint2*)&Bsn[(kb + 32) * SBH + n4 * 4] = make_uint2(fh2(pb2.x, pb2.y), fh2(pb2.z, pb2.w));
            *(uint2*)&Bsn[(kb + 48) * SBH + n4 * 4] = make_uint2(fh2(pb3.x, pb3.y), fh2(pb3.z, pb3.w));
        }
        __syncthreads();
    }

    // Epilogue: c0/c1 -> (row, 2lc..2lc+1), c2/c3 -> (row+8, ...)
#pragma unroll
    for (int mi = 0; mi < 2; mi++) {
#pragma unroll
        for (int ni = 0; ni < 4; ni++) {
            const int row = bm + wm + mi * 16 + lr;
            const int col = bn + wn + ni * 8 + lc * 2;
            *(float2*)(Cout + (size_t)row * N + col) =
                make_float2(acc[mi][ni][0], acc[mi][ni][1]);
            *(float2*)(Cout + (size_t)(row + 8) * N + col) =
                make_float2(acc[mi][ni][2], acc[mi][ni][3]);
        }
    }
}

__global__ __launch_bounds__(512, 1) void qkv_gemm_mma(const float* __restrict__ x,
                                                       const float* __restrict__ W_attn) {
    gemm_mma(x, W_attn, g_qkv, MT_, C3_, C_);
}
__global__ __launch_bounds__(512, 1) void proj_gemm_mma(const float* __restrict__ W_proj,
                                                        float* __restrict__ out) {
    gemm_mma(g_y, W_proj, out, MT_, C_, C_);
}

// ---------------------------------------------------------------------------
// fp16 tensor-core causal flash attention (UNCHANGED from round 12 — passing).
// ---------------------------------------------------------------------------
#define PADH 72
#define ATT2_SMEM ((128 * PADH + 64 * PADH + 64 * PADH + 128 * PADH) * 2)  // 55296

__global__ __launch_bounds__(256, 2) void attn_mma_kernel()
{
    extern __shared__ __align__(16) char smraw[];
    __half* Qs = (__half*)smraw;            // [128][72]
    __half* Ks = Qs + 128 * PADH;           // [64][72]
    __half* Vs = Ks + 64 * PADH;            // [64][72]
    __half* Ps = Vs + 64 * PADH;            // [128][72]

    const int tid  = threadIdx.x;
    const int wid  = tid >> 5;
    const int lane = tid & 31;
    const int lr   = lane >> 2;
    const int lc   = lane & 3;
    const int qt   = (int)gridDim.x - 1 - (int)blockIdx.x;  // heavy tiles first
    const int h    = blockIdx.y;
    const int b    = blockIdx.z;
    const int q0   = qt * 128;
    const int wq   = wid * 16;
    const float scale = 0.125f;

    const float* qbase = g_qkv + (size_t)(b * T_ + q0) * C3_ + h * D_;
#pragma unroll
    for (int i = 0; i < 8; i++) {
        const int idx = tid + i * 256;
        const int row = idx >> 4;
        const int c4  = (idx & 15) << 2;
        float4 v = *(const float4*)(qbase + (size_t)row * C3_ + c4);
        *(uint2*)&Qs[row * PADH + c4] = make_uint2(fh2(v.x, v.y), fh2(v.z, v.w));
    }

    float m0 = -1e30f, m1 = -1e30f, l0 = 0.f, l1 = 0.f;
    float o[8][4];
#pragma unroll
    for (int dt = 0; dt < 8; dt++)
#pragma unroll
        for (int f = 0; f < 4; f++) o[dt][f] = 0.f;

    const int qr0 = q0 + wq + lr;
    const int qr1 = qr0 + 8;
    const int nkt = 2 * qt + 2;

    const int vd4 = tid & 15;     // d-col group
    const int vkp = tid >> 4;     // key-pair

    for (int kt = 0; kt < nkt; kt++) {
        const int k0 = kt * 64;
        const float* kbase = g_qkv + (size_t)(b * T_ + k0) * C3_ + C_ + h * D_;
        const float* vbase = kbase + C_;

        __syncthreads();
#pragma unroll
        for (int i = 0; i < 4; i++) {
            const int idx = tid + i * 256;
            const int row = idx >> 4;
            const int c4  = (idx & 15) << 2;
            float4 kv = *(const float4*)(kbase + (size_t)row * C3_ + c4);
            *(uint2*)&Ks[row * PADH + c4] = make_uint2(fh2(kv.x, kv.y), fh2(kv.z, kv.w));
        }
#pragma unroll
        for (int i = 0; i < 2; i++) {
            const int kpair = vkp + i * 16;
            const float* v0p = vbase + (size_t)(2 * kpair) * C3_ + vd4 * 4;
            const float* v1p = v0p + C3_;
            float4 v0 = *(const float4*)v0p;
            float4 v1 = *(const float4*)v1p;
            *(uint32_t*)&Vs[(4 * vd4 + 0) * PADH + 2 * kpair] = fh2(v0.x, v1.x);
            *(uint32_t*)&Vs[(4 * vd4 + 1) * PADH + 2 * kpair] = fh2(v0.y, v1.y);
            *(uint32_t*)&Vs[(4 * vd4 + 2) * PADH + 2 * kpair] = fh2(v0.z, v1.z);
            *(uint32_t*)&Vs[(4 * vd4 + 3) * PADH + 2 * kpair] = fh2(v0.w, v1.w);
        }
        __syncthreads();

        if (k0 <= q0 + wq + 15) {
            float s[8][4];
#pragma unroll
            for (int nt = 0; nt < 8; nt++)
#pragma unroll
                for (int f = 0; f < 4; f++) s[nt][f] = 0.f;

#pragma unroll
            for (int ks = 0; ks < 4; ks++) {
                const int koh = ks * 16;
                const uint32_t a0 = *(const uint32_t*)&Qs[(wq + lr) * PADH + koh + 2 * lc];
                const uint32_t a1 = *(const uint32_t*)&Qs[(wq + lr + 8) * PADH + koh + 2 * lc];
                const uint32_t a2 = *(const uint32_t*)&Qs[(wq + lr) * PADH + koh + 2 * lc + 8];
                const uint32_t a3 = *(const uint32_t*)&Qs[(wq + lr + 8) * PADH + koh + 2 * lc + 8];
#pragma unroll
                for (int nt = 0; nt < 8; nt++) {
                    const int ncol = nt * 8 + lr;
                    const uint32_t b0 = *(const uint32_t*)&Ks[ncol * PADH + koh + 2 * lc];
                    const uint32_t b1 = *(const uint32_t*)&Ks[ncol * PADH + koh + 2 * lc + 8];
                    mma_f16(s[nt][0], s[nt][1], s[nt][2], s[nt][3], a0, a1, a2, a3, b0, b1);
                }
            }

            const bool need_mask = (k0 + 63 > q0 + wq);
            float rmax0 = -1e30f, rmax1 = -1e30f;
#pragma unroll
            for (int nt = 0; nt < 8; nt++) {
                const int kcol = k0 + nt * 8 + 2 * lc;
                float v0 = s[nt][0] * scale, v1 = s[nt][1] * scale;
                float v2 = s[nt][2] * scale, v3 = s[nt][3] * scale;
                if (need_mask) {
                    if (kcol     > qr0) v0 = -1e30f;
                    if (kcol + 1 > qr0) v1 = -1e30f;
                    if (kcol     > qr1) v2 = -1e30f;
                    if (kcol + 1 > qr1) v3 = -1e30f;
                }
                s[nt][0] = v0; s[nt][1] = v1; s[nt][2] = v2; s[nt][3] = v3;
                rmax0 = fmaxf(rmax0, fmaxf(v0, v1));
                rmax1 = fmaxf(rmax1, fmaxf(v2, v3));
            }
            rmax0 = fmaxf(rmax0, __shfl_xor_sync(0xffffffffu, rmax0, 1));
            rmax0 = fmaxf(rmax0, __shfl_xor_sync(0xffffffffu, rmax0, 2));
            rmax1 = fmaxf(rmax1, __shfl_xor_sync(0xffffffffu, rmax1, 1));
            rmax1 = fmaxf(rmax1, __shfl_xor_sync(0xffffffffu, rmax1, 2));

            const float mn0 = fmaxf(m0, rmax0);
            const float mn1 = fmaxf(m1, rmax1);
            const float alpha0 = __expf(m0 - mn0);
            const float alpha1 = __expf(m1 - mn1);

            float sum0 = 0.f, sum1 = 0.f;
#pragma unroll
            for (int nt = 0; nt < 8; nt++) {
                const float p0 = __expf(s[nt][0] - mn0);
                const float p1 = __expf(s[nt][1] - mn0);
                const float p2 = __expf(s[nt][2] - mn1);
                const float p3 = __expf(s[nt][3] - mn1);
                s[nt][0] = p0; s[nt][1] = p1; s[nt][2] = p2; s[nt][3] = p3;
                sum0 += p0 + p1;
                sum1 += p2 + p3;
            }
            sum0 += __shfl_xor_sync(0xffffffffu, sum0, 1);
            sum0 += __shfl_xor_sync(0xffffffffu, sum0, 2);
            sum1 += __shfl_xor_sync(0xffffffffu, sum1, 1);
            sum1 += __shfl_xor_sync(0xffffffffu, sum1, 2);

            l0 = l0 * alpha0 + sum0;
            l1 = l1 * alpha1 + sum1;
            m0 = mn0; m1 = mn1;

#pragma unroll
            for (int dt = 0; dt < 8; dt++) {
                o[dt][0] *= alpha0; o[dt][1] *= alpha0;
                o[dt][2] *= alpha1; o[dt][3] *= alpha1;
            }

#pragma unroll
            for (int nt = 0; nt < 8; nt++) {
                *(uint32_t*)&Ps[(wq + lr) * PADH + nt * 8 + 2 * lc] =
                    fh2(s[nt][0], s[nt][1]);
                *(uint32_t*)&Ps[(wq + lr + 8) * PADH + nt * 8 + 2 * lc] =
                    fh2(s[nt][2], s[nt][3]);
            }
            __syncwarp();

#pragma unroll
            for (int ks = 0; ks < 4; ks++) {
                const int koh = ks * 16;
                const uint32_t a0 = *(const uint32_t*)&Ps[(wq + lr) * PADH + koh + 2 * lc];
                const uint32_t a1 = *(const uint32_t*)&Ps[(wq + lr + 8) * PADH + koh + 2 * lc];
                const uint32_t a2 = *(const uint32_t*)&Ps[(wq + lr) * PADH + koh + 2 * lc + 8];
                const uint32_t a3 = *(const uint32_t*)&Ps[(wq + lr + 8) * PADH + koh + 2 * lc + 8];
#pragma unroll
                for (int dt = 0; dt < 8; dt++) {
                    const int dcol = dt * 8 + lr;
                    const uint32_t b0 = *(const uint32_t*)&Vs[dcol * PADH + koh + 2 * lc];
                    const uint32_t b1 = *(const uint32_t*)&Vs[dcol * PADH + koh + 2 * lc + 8];
                    mma_f16(o[dt][0], o[dt][1], o[dt][2], o[dt][3], a0, a1, a2, a3, b0, b1);
                }
            }
        }
    }

    const float inv0 = 1.0f / l0;
    const float inv1 = 1.0f / l1;
    float* y0 = g_y + (size_t)(b * T_ + qr0) * C_ + h * D_;
    float* y1 = g_y + (size_t)(b * T_ + qr1) * C_ + h * D_;
#pragma unroll
    for (int dt = 0; dt < 8; dt++) {
        const int col = dt * 8 + 2 * lc;
        *(float2*)(y0 + col) = make_float2(o[dt][0] * inv0, o[dt][1] * inv0);
        *(float2*)(y1 + col) = make_float2(o[dt][2] * inv1, o[dt][3] * inv1);
    }
}

// ---------------------------------------------------------------------------
// Launch
// ---------------------------------------------------------------------------
extern "C" void kernel_launch(void* const* d_in, const int* in_sizes, int n_in,
                              void* d_out, int out_size)
{
    const float* x      = (const float*)d_in[0];   // [M, C]
    const float* W_attn = (const float*)d_in[1];   // [C, 3C]
    const float* W_proj = (const float*)d_in[2];   // [C, C]
    float* out = (float*)d_out;                    // [M, C]

    cudaFuncSetAttribute(qkv_gemm_mma,    cudaFuncAttributeMaxDynamicSharedMemorySize, GEMM_SMEM);
    cudaFuncSetAttribute(proj_gemm_mma,   cudaFuncAttributeMaxDynamicSharedMemorySize, GEMM_SMEM);
    cudaFuncSetAttribute(attn_mma_kernel, cudaFuncAttributeMaxDynamicSharedMemorySize, ATT2_SMEM);

    // 1) QKV = x @ W_attn   (fp16 mma.sync + ldmatrix, KC=64, 512 threads)
    {
        dim3 grid(C3_ / 128, MT_ / 128);   // (24, 64)
        qkv_gemm_mma<<<grid, 512, GEMM_SMEM>>>(x, W_attn);
    }
    // 2) attention (fp16 mma.sync, fp32 softmax)
    {
        dim3 grid(T_ / 128, H_, B_);       // (16, 16, 4)
        attn_mma_kernel<<<grid, 256, ATT2_SMEM>>>();
    }
    // 3) out = y @ W_proj   (fp16 mma.sync + ldmatrix, KC=64, 512 threads)
    {
        dim3 grid(C_ / 128, MT_ / 128);    // (8, 64)
        proj_gemm_mma<<<grid, 512, GEMM_SMEM>>>(W_proj, out);
    }
}

// round 17
// speedup vs baseline: 1.1990x; 1.0749x over previous
#include <cuda_runtime.h>
#include <cuda_fp16.h>
#include <cstdint>
#include <cstddef>

// Problem constants
#define B_ 4
#define T_ 2048
#define C_ 1024
#define H_ 16
#define D_ 64
#define C3_ 3072
#define MT_ 8192        // B*T

// Scratch — round-2 set (proven to pass the checker)
__device__ float g_qkv[(size_t)MT_ * C3_];   // [M, 3C]  96 MB
__device__ float g_y[(size_t)MT_ * C_];      // [M, C]   32 MB

// ---------------------------------------------------------------------------
// Helpers
// ---------------------------------------------------------------------------
__device__ __forceinline__ uint32_t fh2(float lo, float hi) {
    __half2 t = __floats2half2_rn(lo, hi);
    return *(uint32_t*)&t;
}
__device__ __forceinline__ uint32_t smem_u32(const void* p) {
    uint32_t a;
    asm("{ .reg .u64 t; cvta.to.shared.u64 t, %1; cvt.u32.u64 %0, t; }" : "=r"(a) : "l"(p));
    return a;
}
__device__ __forceinline__ void mma_f16(float& c0, float& c1, float& c2, float& c3,
                                        uint32_t a0, uint32_t a1, uint32_t a2, uint32_t a3,
                                        uint32_t b0, uint32_t b1) {
    asm volatile(
        "mma.sync.aligned.m16n8k16.row.col.f32.f16.f16.f32 "
        "{%0,%1,%2,%3}, {%4,%5,%6,%7}, {%8,%9}, {%0,%1,%2,%3};"
        : "+f"(c0), "+f"(c1), "+f"(c2), "+f"(c3)
        : "r"(a0), "r"(a1), "r"(a2), "r"(a3), "r"(b0), "r"(b1));
}
__device__ __forceinline__ void ldsm_x4(uint32_t& r0, uint32_t& r1, uint32_t& r2, uint32_t& r3,
                                        uint32_t addr) {
    asm volatile("ldmatrix.sync.aligned.m8n8.x4.shared.b16 {%0,%1,%2,%3}, [%4];"
                 : "=r"(r0), "=r"(r1), "=r"(r2), "=r"(r3) : "r"(addr));
}
__device__ __forceinline__ void ldsm_x4_t(uint32_t& r0, uint32_t& r1, uint32_t& r2, uint32_t& r3,
                                          uint32_t addr) {
    asm volatile("ldmatrix.sync.aligned.m8n8.x4.trans.shared.b16 {%0,%1,%2,%3}, [%4];"
                 : "=r"(r0), "=r"(r1), "=r"(r2), "=r"(r3) : "r"(addr));
}

// ---------------------------------------------------------------------------
// fp16 mma.sync GEMM (UNCHANGED from round 16 — passing, 247us/68us).
// CTA 128x128 (16 warps 4x4, warp tile 32x32), K-chunk 64, 2-stage dbuf.
// ---------------------------------------------------------------------------
#define KC 64
#define SAH 72                               // A row stride (halves)
#define SBH 136                              // B row stride (halves)
#define A_BYTES (128 * SAH * 2)              // 18432
#define B_BYTES (KC * SBH * 2)               // 17408
#define STAGE_BYTES (A_BYTES + B_BYTES)      // 35840
#define GEMM_SMEM (2 * STAGE_BYTES)          // 71680

__device__ __forceinline__ void gemm_mma(
    const float* __restrict__ A, const float* __restrict__ W,
    float* __restrict__ Cout, int M, int N, int K)
{
    extern __shared__ __align__(16) char smraw[];
    const uint32_t smA = smem_u32(smraw);

    const int tid  = threadIdx.x;
    const int wid  = tid >> 5;
    const int lane = tid & 31;
    const int lr   = lane >> 2;
    const int lc   = lane & 3;
    const int bm   = blockIdx.y * 128;
    const int bn   = blockIdx.x * 128;
    const int wm   = (wid >> 2) * 32;
    const int wn   = (wid & 3) * 32;

    const int NC = K / KC;

    const int mrow8 = ((lane >> 3) & 1) * 8 + (lane & 7);
    const int half8 = (lane >> 4) * 8;
    const uint32_t aoff = (uint32_t)(mrow8 * SAH + half8) * 2;
    const uint32_t boff = (uint32_t)(mrow8 * SBH + half8) * 2;

    float acc[2][4][4];
#pragma unroll
    for (int mi = 0; mi < 2; mi++)
#pragma unroll
        for (int ni = 0; ni < 4; ni++)
#pragma unroll
            for (int f = 0; f < 4; f++) acc[mi][ni][f] = 0.f;

    const int ra = tid >> 4;
    const int kq = tid & 15;
    const float* Ap = A + (size_t)(bm + ra) * K + kq * 4;
    const int kb = tid >> 5;
    const int n4 = tid & 31;
    const float* Wp = W + (size_t)kb * N + bn + n4 * 4;

    float4 pa0 = *(const float4*)(Ap);
    float4 pa1 = *(const float4*)(Ap + (size_t)32 * K);
    float4 pa2 = *(const float4*)(Ap + (size_t)64 * K);
    float4 pa3 = *(const float4*)(Ap + (size_t)96 * K);
    float4 pb0 = *(const float4*)(Wp);
    float4 pb1 = *(const float4*)(Wp + (size_t)16 * N);
    float4 pb2 = *(const float4*)(Wp + (size_t)32 * N);
    float4 pb3 = *(const float4*)(Wp + (size_t)48 * N);

    {
        __half* As = (__half*)smraw;
        __half* Bs = (__half*)(smraw + A_BYTES);
        *(uint2*)&As[ra * SAH + kq * 4]        = make_uint2(fh2(pa0.x, pa0.y), fh2(pa0.z, pa0.w));
        *(uint2*)&As[(ra + 32) * SAH + kq * 4] = make_uint2(fh2(pa1.x, pa1.y), fh2(pa1.z, pa1.w));
        *(uint2*)&As[(ra + 64) * SAH + kq * 4] = make_uint2(fh2(pa2.x, pa2.y), fh2(pa2.z, pa2.w));
        *(uint2*)&As[(ra + 96) * SAH + kq * 4] = make_uint2(fh2(pa3.x, pa3.y), fh2(pa3.z, pa3.w));
        *(uint2*)&Bs[kb * SBH + n4 * 4]        = make_uint2(fh2(pb0.x, pb0.y), fh2(pb0.z, pb0.w));
        *(uint2*)&Bs[(kb + 16) * SBH + n4 * 4] = make_uint2(fh2(pb1.x, pb1.y), fh2(pb1.z, pb1.w));
        *(uint2*)&Bs[(kb + 32) * SBH + n4 * 4] = make_uint2(fh2(pb2.x, pb2.y), fh2(pb2.z, pb2.w));
        *(uint2*)&Bs[(kb + 48) * SBH + n4 * 4] = make_uint2(fh2(pb3.x, pb3.y), fh2(pb3.z, pb3.w));
    }
    __syncthreads();

    for (int c = 0; c < NC; c++) {
        const bool more = (c + 1 < NC);
        if (more) {
            const int go = (c + 1) * KC;
            pa0 = *(const float4*)(Ap + go);
            pa1 = *(const float4*)(Ap + (size_t)32 * K + go);
            pa2 = *(const float4*)(Ap + (size_t)64 * K + go);
            pa3 = *(const float4*)(Ap + (size_t)96 * K + go);
            const size_t wgo = (size_t)(c + 1) * KC * N;
            pb0 = *(const float4*)(Wp + wgo);
            pb1 = *(const float4*)(Wp + wgo + (size_t)16 * N);
            pb2 = *(const float4*)(Wp + wgo + (size_t)32 * N);
            pb3 = *(const float4*)(Wp + wgo + (size_t)48 * N);
        }

        const uint32_t As0 = smA + (c & 1) * STAGE_BYTES;
        const uint32_t Bs0 = As0 + A_BYTES;
#pragma unroll
        for (int ks = 0; ks < 4; ks++) {
            const int koh = ks * 16;
            uint32_t a[2][4], b[4][2];
#pragma unroll
            for (int mi = 0; mi < 2; mi++)
                ldsm_x4(a[mi][0], a[mi][1], a[mi][2], a[mi][3],
                        As0 + (uint32_t)((wm + mi * 16) * SAH + koh) * 2 + aoff);
            ldsm_x4_t(b[0][0], b[0][1], b[1][0], b[1][1],
                      Bs0 + (uint32_t)(koh * SBH + wn) * 2 + boff);
            ldsm_x4_t(b[2][0], b[2][1], b[3][0], b[3][1],
                      Bs0 + (uint32_t)(koh * SBH + wn + 16) * 2 + boff);
#pragma unroll
            for (int mi = 0; mi < 2; mi++)
#pragma unroll
                for (int ni = 0; ni < 4; ni++)
                    mma_f16(acc[mi][ni][0], acc[mi][ni][1], acc[mi][ni][2], acc[mi][ni][3],
                            a[mi][0], a[mi][1], a[mi][2], a[mi][3], b[ni][0], b[ni][1]);
        }

        if (more) {
            __half* Asn = (__half*)(smraw + ((c + 1) & 1) * STAGE_BYTES);
            __half* Bsn = (__half*)(smraw + ((c + 1) & 1) * STAGE_BYTES + A_BYTES);
            *(uint2*)&Asn[ra * SAH + kq * 4]        = make_uint2(fh2(pa0.x, pa0.y), fh2(pa0.z, pa0.w));
            *(uint2*)&Asn[(ra + 32) * SAH + kq * 4] = make_uint2(fh2(pa1.x, pa1.y), fh2(pa1.z, pa1.w));
            *(uint2*)&Asn[(ra + 64) * SAH + kq * 4] = make_uint2(fh2(pa2.x, pa2.y), fh2(pa2.z, pa2.w));
            *(uint2*)&Asn[(ra + 96) * SAH + kq * 4] = make_uint2(fh2(pa3.x, pa3.y), fh2(pa3.z, pa3.w));
            *(uint2*)&Bsn[kb * SBH + n4 * 4]        = make_uint2(fh2(pb0.x, pb0.y), fh2(pb0.z, pb0.w));
            *(uint2*)&Bsn[(kb + 16) * SBH + n4 * 4] = make_uint2(fh2(pb1.x, pb1.y), fh2(pb1.z, pb1.w));
            *(uint2*)&Bsn[(kb + 32) * SBH + n4 * 4] = make_uint2(fh2(pb2.x, pb2.y), fh2(pb2.z, pb2.w));
            *(uint2*)&Bsn[(kb + 48) * SBH + n4 * 4] = make_uint2(fh2(pb3.x, pb3.y), fh2(pb3.z, pb3.w));
        }
        __syncthreads();
    }

#pragma unroll
    for (int mi = 0; mi < 2; mi++) {
#pragma unroll
        for (int ni = 0; ni < 4; ni++) {
            const int row = bm + wm + mi * 16 + lr;
            const int col = bn + wn + ni * 8 + lc * 2;
            *(float2*)(Cout + (size_t)row * N + col) =
                make_float2(acc[mi][ni][0], acc[mi][ni][1]);
            *(float2*)(Cout + (size_t)(row + 8) * N + col) =
                make_float2(acc[mi][ni][2], acc[mi][ni][3]);
        }
    }
}

__global__ __launch_bounds__(512, 1) void qkv_gemm_mma(const float* __restrict__ x,
                                                       const float* __restrict__ W_attn) {
    gemm_mma(x, W_attn, g_qkv, MT_, C3_, C_);
}
__global__ __launch_bounds__(512, 1) void proj_gemm_mma(const float* __restrict__ W_proj,
                                                        float* __restrict__ out) {
    gemm_mma(g_y, W_proj, out, MT_, C_, C_);
}

// ---------------------------------------------------------------------------
// fp16 tensor-core causal flash attention, ldmatrix fragment loads.
// CTA 128 q-rows, K-tile 64, D=64; 8 warps; 2 CTAs/SM.
// Smem (halves, stride 72): Qs[128][72], Ks[64][72] (key-major, d contig),
// Vs[64][72] (key-major, d contig — SAME loader as K, conflict-free),
// Ps[128][72].
// Fragments: Q/P non-trans ldsm (A-frags); K non-trans ldsm ([n][k] layout
// gives b-pairs directly); V trans ldsm (GEMM-B recipe, [k][n] layout).
// Stride 72 -> ldsm group step 9 ≡ 1 (mod 8): conflict-free everywhere.
// ---------------------------------------------------------------------------
#define PADH 72
#define ATT2_SMEM ((128 * PADH + 64 * PADH + 64 * PADH + 128 * PADH) * 2)  // 55296

__global__ __launch_bounds__(256, 2) void attn_mma_kernel()
{
    extern __shared__ __align__(16) char smraw[];
    __half* Qs = (__half*)smraw;            // [128][72]
    __half* Ks = Qs + 128 * PADH;           // [64][72]
    __half* Vs = Ks + 64 * PADH;            // [64][72]
    __half* Ps = Vs + 64 * PADH;            // [128][72]
    const uint32_t sQ = smem_u32(Qs);
    const uint32_t sK = smem_u32(Ks);
    const uint32_t sV = smem_u32(Vs);
    const uint32_t sP = smem_u32(Ps);

    const int tid  = threadIdx.x;
    const int wid  = tid >> 5;
    const int lane = tid & 31;
    const int lr   = lane >> 2;
    const int lc   = lane & 3;
    const int qt   = (int)gridDim.x - 1 - (int)blockIdx.x;  // heavy tiles first
    const int h    = blockIdx.y;
    const int b    = blockIdx.z;
    const int q0   = qt * 128;
    const int wq   = wid * 16;
    const float scale = 0.125f;

    // ldmatrix lane-offset (bytes), stride 72 halves — shared by all tiles.
    const int mrow8 = ((lane >> 3) & 1) * 8 + (lane & 7);
    const int half8 = (lane >> 4) * 8;
    const uint32_t loff = (uint32_t)(mrow8 * PADH + half8) * 2;

    // Load Q tile [128 x 64] -> half
    const float* qbase = g_qkv + (size_t)(b * T_ + q0) * C3_ + h * D_;
#pragma unroll
    for (int i = 0; i < 8; i++) {
        const int idx = tid + i * 256;
        const int row = idx >> 4;
        const int c4  = (idx & 15) << 2;
        float4 v = *(const float4*)(qbase + (size_t)row * C3_ + c4);
        *(uint2*)&Qs[row * PADH + c4] = make_uint2(fh2(v.x, v.y), fh2(v.z, v.w));
    }

    float m0 = -1e30f, m1 = -1e30f, l0 = 0.f, l1 = 0.f;
    float o[8][4];
#pragma unroll
    for (int dt = 0; dt < 8; dt++)
#pragma unroll
        for (int f = 0; f < 4; f++) o[dt][f] = 0.f;

    const int qr0 = q0 + wq + lr;
    const int qr1 = qr0 + 8;
    const int nkt = 2 * qt + 2;

    for (int kt = 0; kt < nkt; kt++) {
        const int k0 = kt * 64;
        const float* kbase = g_qkv + (size_t)(b * T_ + k0) * C3_ + C_ + h * D_;
        const float* vbase = kbase + C_;

        __syncthreads();   // prior-iter Ks/Vs reads complete
        // K and V tiles: identical coalesced conflict-free loaders (key-major)
#pragma unroll
        for (int i = 0; i < 4; i++) {
            const int idx = tid + i * 256;
            const int row = idx >> 4;
            const int c4  = (idx & 15) << 2;
            float4 kv = *(const float4*)(kbase + (size_t)row * C3_ + c4);
            *(uint2*)&Ks[row * PADH + c4] = make_uint2(fh2(kv.x, kv.y), fh2(kv.z, kv.w));
            float4 vv = *(const float4*)(vbase + (size_t)row * C3_ + c4);
            *(uint2*)&Vs[row * PADH + c4] = make_uint2(fh2(vv.x, vv.y), fh2(vv.z, vv.w));
        }
        __syncthreads();

        if (k0 <= q0 + wq + 15) {
            // ---- S = Q K^T (16 x 64 per warp), ldmatrix frags ----
            float s[8][4];
#pragma unroll
            for (int nt = 0; nt < 8; nt++)
#pragma unroll
                for (int f = 0; f < 4; f++) s[nt][f] = 0.f;

#pragma unroll
            for (int ks = 0; ks < 4; ks++) {
                const int koh = ks * 16;
                uint32_t a0, a1, a2, a3;
                ldsm_x4(a0, a1, a2, a3, sQ + (uint32_t)(wq * PADH + koh) * 2 + loff);
                uint32_t bk[8][2];
#pragma unroll
                for (int np = 0; np < 4; np++)
                    ldsm_x4(bk[2 * np][0], bk[2 * np + 1][0], bk[2 * np][1], bk[2 * np + 1][1],
                            sK + (uint32_t)(np * 16 * PADH + koh) * 2 + loff);
#pragma unroll
                for (int nt = 0; nt < 8; nt++)
                    mma_f16(s[nt][0], s[nt][1], s[nt][2], s[nt][3],
                            a0, a1, a2, a3, bk[nt][0], bk[nt][1]);
            }

            // ---- scale + causal mask + online softmax (fp32) ----
            const bool need_mask = (k0 + 63 > q0 + wq);
            float rmax0 = -1e30f, rmax1 = -1e30f;
#pragma unroll
            for (int nt = 0; nt < 8; nt++) {
                const int kcol = k0 + nt * 8 + 2 * lc;
                float v0 = s[nt][0] * scale, v1 = s[nt][1] * scale;
                float v2 = s[nt][2] * scale, v3 = s[nt][3] * scale;
                if (need_mask) {
                    if (kcol     > qr0) v0 = -1e30f;
                    if (kcol + 1 > qr0) v1 = -1e30f;
                    if (kcol     > qr1) v2 = -1e30f;
                    if (kcol + 1 > qr1) v3 = -1e30f;
                }
                s[nt][0] = v0; s[nt][1] = v1; s[nt][2] = v2; s[nt][3] = v3;
                rmax0 = fmaxf(rmax0, fmaxf(v0, v1));
                rmax1 = fmaxf(rmax1, fmaxf(v2, v3));
            }
            rmax0 = fmaxf(rmax0, __shfl_xor_sync(0xffffffffu, rmax0, 1));
            rmax0 = fmaxf(rmax0, __shfl_xor_sync(0xffffffffu, rmax0, 2));
            rmax1 = fmaxf(rmax1, __shfl_xor_sync(0xffffffffu, rmax1, 1));
            rmax1 = fmaxf(rmax1, __shfl_xor_sync(0xffffffffu, rmax1, 2));

            const float mn0 = fmaxf(m0, rmax0);
            const float mn1 = fmaxf(m1, rmax1);
            const float alpha0 = __expf(m0 - mn0);
            const float alpha1 = __expf(m1 - mn1);

            float sum0 = 0.f, sum1 = 0.f;
#pragma unroll
            for (int nt = 0; nt < 8; nt++) {
                const float p0 = __expf(s[nt][0] - mn0);
                const float p1 = __expf(s[nt][1] - mn0);
                const float p2 = __expf(s[nt][2] - mn1);
                const float p3 = __expf(s[nt][3] - mn1);
                s[nt][0] = p0; s[nt][1] = p1; s[nt][2] = p2; s[nt][3] = p3;
                sum0 += p0 + p1;
                sum1 += p2 + p3;
            }
            sum0 += __shfl_xor_sync(0xffffffffu, sum0, 1);
            sum0 += __shfl_xor_sync(0xffffffffu, sum0, 2);
            sum1 += __shfl_xor_sync(0xffffffffu, sum1, 1);
            sum1 += __shfl_xor_sync(0xffffffffu, sum1, 2);

            l0 = l0 * alpha0 + sum0;
            l1 = l1 * alpha1 + sum1;
            m0 = mn0; m1 = mn1;

#pragma unroll
            for (int dt = 0; dt < 8; dt++) {
                o[dt][0] *= alpha0; o[dt][1] *= alpha0;
                o[dt][2] *= alpha1; o[dt][3] *= alpha1;
            }

            // ---- P -> smem half (store pattern conflict-free, unchanged) ----
#pragma unroll
            for (int nt = 0; nt < 8; nt++) {
                *(uint32_t*)&Ps[(wq + lr) * PADH + nt * 8 + 2 * lc] =
                    fh2(s[nt][0], s[nt][1]);
                *(uint32_t*)&Ps[(wq + lr + 8) * PADH + nt * 8 + 2 * lc] =
                    fh2(s[nt][2], s[nt][3]);
            }
            __syncwarp();

            // ---- O += P V, ldmatrix frags (V trans) ----
#pragma unroll
            for (int ks = 0; ks < 4; ks++) {
                const int koh = ks * 16;
                uint32_t a0, a1, a2, a3;
                ldsm_x4(a0, a1, a2, a3, sP + (uint32_t)(wq * PADH + koh) * 2 + loff);
                uint32_t bv[8][2];
#pragma unroll
                for (int dp = 0; dp < 4; dp++)
                    ldsm_x4_t(bv[2 * dp][0], bv[2 * dp][1], bv[2 * dp + 1][0], bv[2 * dp + 1][1],
                              sV + (uint32_t)(koh * PADH + dp * 16) * 2 + loff);
#pragma unroll
                for (int dt = 0; dt < 8; dt++)
                    mma_f16(o[dt][0], o[dt][1], o[dt][2], o[dt][3],
                            a0, a1, a2, a3, bv[dt][0], bv[dt][1]);
            }
        }
    }

    // Epilogue: normalize, write y
    const float inv0 = 1.0f / l0;
    const float inv1 = 1.0f / l1;
    float* y0 = g_y + (size_t)(b * T_ + qr0) * C_ + h * D_;
    float* y1 = g_y + (size_t)(b * T_ + qr1) * C_ + h * D_;
#pragma unroll
    for (int dt = 0; dt < 8; dt++) {
        const int col = dt * 8 + 2 * lc;
        *(float2*)(y0 + col) = make_float2(o[dt][0] * inv0, o[dt][1] * inv0);
        *(float2*)(y1 + col) = make_float2(o[dt][2] * inv1, o[dt][3] * inv1);
    }
}

// ---------------------------------------------------------------------------
// Launch
// ---------------------------------------------------------------------------
extern "C" void kernel_launch(void* const* d_in, const int* in_sizes, int n_in,
                              void* d_out, int out_size)
{
    const float* x      = (const float*)d_in[0];   // [M, C]
    const float* W_attn = (const float*)d_in[1];   // [C, 3C]
    const float* W_proj = (const float*)d_in[2];   // [C, C]
    float* out = (float*)d_out;                    // [M, C]

    cudaFuncSetAttribute(qkv_gemm_mma,    cudaFuncAttributeMaxDynamicSharedMemorySize, GEMM_SMEM);
    cudaFuncSetAttribute(proj_gemm_mma,   cudaFuncAttributeMaxDynamicSharedMemorySize, GEMM_SMEM);
    cudaFuncSetAttribute(attn_mma_kernel, cudaFuncAttributeMaxDynamicSharedMemorySize, ATT2_SMEM);

    // 1) QKV = x @ W_attn   (fp16 mma.sync + ldmatrix, KC=64, 512 threads)
    {
        dim3 grid(C3_ / 128, MT_ / 128);   // (24, 64)
        qkv_gemm_mma<<<grid, 512, GEMM_SMEM>>>(x, W_attn);
    }
    // 2) attention (fp16 mma.sync + ldmatrix, fp32 softmax)
    {
        dim3 grid(T_ / 128, H_, B_);       // (16, 16, 4)
        attn_mma_kernel<<<grid, 256, ATT2_SMEM>>>();
    }
    // 3) out = y @ W_proj   (fp16 mma.sync + ldmatrix, KC=64, 512 threads)
    {
        dim3 grid(C_ / 128, MT_ / 128);    // (8, 64)
        proj_gemm_mma<<<grid, 512, GEMM_SMEM>>>(W_proj, out);
    }
}